// round 1
// baseline (speedup 1.0000x reference)
#include <cuda_runtime.h>
#include <math.h>

// Problem constants
#define NB_B   2
#define NB_C   128
#define NB_H   160
#define NB_W   160
#define NB_HW  (NB_H*NB_W)
#define NB_N   256
#define NB_P   7
#define NB_BIN 49
#define NB_KIN 6272     // C*P*P
#define NB_DF  1024
#define POOL_SCALE 0.0625f
#define TRANS_STD  0.1f

// Scratch (static device globals; no runtime allocation)
__device__ float g_dataT[NB_B*NB_HW*NB_C];   // (B,H,W,C) channel-last
__device__ float g_xpool[NB_N*NB_KIN];       // pooled features, layout [n][c*49+bin]
__device__ float g_h1[NB_N*NB_DF];
__device__ float g_m1[NB_N*NB_DF];
__device__ float g_h2[NB_N*NB_DF];
__device__ float g_offs[NB_N*98];            // (N,2,7,7) flattened
__device__ float g_mask[NB_N*NB_BIN];        // (N,7,7)

// ---------------------------------------------------------------------------
// (B,C,H,W) -> (B,H,W,C) tiled transpose
// ---------------------------------------------------------------------------
__global__ void transpose_kernel(const float* __restrict__ src)
{
    __shared__ float t[32][33];
    int b   = blockIdx.z;
    int hw0 = blockIdx.x * 32;
    int c0  = blockIdx.y * 32;
    #pragma unroll
    for (int i = 0; i < 4; i++) {
        int c = c0 + threadIdx.y + i*8;
        t[threadIdx.y + i*8][threadIdx.x] =
            src[(size_t)(b*NB_C + c)*NB_HW + hw0 + threadIdx.x];
    }
    __syncthreads();
    #pragma unroll
    for (int i = 0; i < 4; i++) {
        int hw = hw0 + threadIdx.y + i*8;
        g_dataT[(size_t)(b*NB_HW + hw)*NB_C + c0 + threadIdx.x] =
            t[threadIdx.x][threadIdx.y + i*8];
    }
}

// ---------------------------------------------------------------------------
// Deformable PSRoI pooling. One block per (bin, roi). 128 threads = channels.
// second=0: write g_xpool (canonical c*49+bin layout), no trans.
// second=1: use g_offs as trans, multiply g_mask, write out (N,C,P,P).
// ---------------------------------------------------------------------------
__global__ void pool_kernel(const float* __restrict__ rois,
                            float* __restrict__ out, int second)
{
    __shared__ int   s_o[16], s_dx[16], s_dy[16];
    __shared__ float s_w0[16], s_w1[16], s_w2[16], s_w3[16], s_v[16];

    int bin = blockIdx.x;
    int n   = blockIdx.y;
    int tid = threadIdx.x;
    const float* r = rois + n*5;

    if (tid < 16) {
        int ph = bin / NB_P, pw = bin % NB_P;
        float x1 = rintf(r[1]) * POOL_SCALE - 0.5f;
        float y1 = rintf(r[2]) * POOL_SCALE - 0.5f;
        float x2 = (rintf(r[3]) + 1.0f) * POOL_SCALE - 0.5f;
        float y2 = (rintf(r[4]) + 1.0f) * POOL_SCALE - 0.5f;
        float roi_w = fmaxf(x2 - x1, 0.1f);
        float roi_h = fmaxf(y2 - y1, 0.1f);
        float bin_w = roi_w / (float)NB_P;
        float bin_h = roi_h / (float)NB_P;
        float sub_w = bin_w * 0.25f;
        float sub_h = bin_h * 0.25f;
        float tx = 0.0f, ty = 0.0f;
        if (second) {
            tx = g_offs[n*98 +      bin] * TRANS_STD;
            ty = g_offs[n*98 + 49 + bin] * TRANS_STD;
        }
        float wstart = (float)pw * bin_w + x1 + tx * roi_w;
        float hstart = (float)ph * bin_h + y1 + ty * roi_h;
        int iw = tid & 3, ih = tid >> 2;
        float w = wstart + (float)iw * sub_w;
        float h = hstart + (float)ih * sub_h;
        float v = (w >= -0.5f && w <= (float)NB_W - 0.5f &&
                   h >= -0.5f && h <= (float)NB_H - 0.5f) ? 1.0f : 0.0f;
        w = fminf(fmaxf(w, 0.0f), (float)(NB_W - 1));
        h = fminf(fmaxf(h, 0.0f), (float)(NB_H - 1));
        int x0  = (int)floorf(w);
        int y0  = (int)floorf(h);
        int x1i = min(x0 + 1, NB_W - 1);
        int y1i = min(y0 + 1, NB_H - 1);
        float lx = w - (float)x0;
        float ly = h - (float)y0;
        s_o [tid] = (y0*NB_W + x0) * NB_C;
        s_dx[tid] = (x1i - x0) * NB_C;
        s_dy[tid] = (y1i - y0) * NB_W * NB_C;
        s_w0[tid] = (1.0f-ly)*(1.0f-lx)*v;
        s_w1[tid] = (1.0f-ly)*lx*v;
        s_w2[tid] = ly*(1.0f-lx)*v;
        s_w3[tid] = ly*lx*v;
        s_v [tid] = v;
    }
    __syncthreads();

    float cnt = 0.0f;
    #pragma unroll
    for (int s = 0; s < 16; s++) cnt += s_v[s];

    int bi = (int)r[0];
    const float* base = g_dataT + (size_t)bi*NB_HW*NB_C + tid;  // channel = tid
    float acc = 0.0f;
    #pragma unroll
    for (int s = 0; s < 16; s++) {
        int o = s_o[s], dx = s_dx[s], dy = s_dy[s];
        acc += s_w0[s]*base[o]
             + s_w1[s]*base[o+dx]
             + s_w2[s]*base[o+dy]
             + s_w3[s]*base[o+dy+dx];
    }
    float res = (cnt > 0.0f) ? acc / cnt : 0.0f;
    if (second) {
        res *= g_mask[n*NB_BIN + bin];
        out[(size_t)(n*NB_C + tid)*NB_BIN + bin] = res;
    } else {
        g_xpool[(size_t)n*NB_KIN + tid*NB_BIN + bin] = res;
    }
}

// ---------------------------------------------------------------------------
// fp32 tiled GEMM: C(M,N) = act(A(M,K) @ B(K,N) + bias)
// BM=32, BN=64, BK=32, 256 threads, 2x4 accum per thread.
// act: 0=none, 1=relu, 2=sigmoid
// ---------------------------------------------------------------------------
__device__ __forceinline__ void gemm_body(
    const float* __restrict__ A, const float* __restrict__ B,
    const float* __restrict__ bias, float* __restrict__ C,
    int M, int N, int K, int act, int bx, int by)
{
    __shared__ float As[32][33];
    __shared__ float Bs[32][64];
    int tid = threadIdx.x;
    int tx = tid & 15, ty = tid >> 4;           // compute mapping
    int m0 = by * 32, n0 = bx * 64;
    int arow = tid >> 3;                        // A: 32 rows x (8 float4)
    int acol = (tid & 7) << 2;
    int brow = tid >> 4;                        // B: 16 rows x (16 float4), x2
    int bcol = (tid & 15) << 2;
    bool nvec = ((N & 3) == 0);                 // row stride 16B-aligned?

    float acc[2][4] = {{0.f,0.f,0.f,0.f},{0.f,0.f,0.f,0.f}};

    for (int k0 = 0; k0 < K; k0 += 32) {
        float4 av = *reinterpret_cast<const float4*>(
            A + (size_t)(m0 + arow)*K + k0 + acol);
        As[acol+0][arow] = av.x; As[acol+1][arow] = av.y;
        As[acol+2][arow] = av.z; As[acol+3][arow] = av.w;
        #pragma unroll
        for (int rr = 0; rr < 2; rr++) {
            int kk = brow + rr*16;
            const float* bp = B + (size_t)(k0 + kk)*N + n0 + bcol;
            float4 bv;
            if (nvec && (n0 + bcol + 3 < N)) {
                bv = *reinterpret_cast<const float4*>(bp);
            } else {
                bv.x = (n0+bcol+0 < N) ? bp[0] : 0.0f;
                bv.y = (n0+bcol+1 < N) ? bp[1] : 0.0f;
                bv.z = (n0+bcol+2 < N) ? bp[2] : 0.0f;
                bv.w = (n0+bcol+3 < N) ? bp[3] : 0.0f;
            }
            *reinterpret_cast<float4*>(&Bs[kk][bcol]) = bv;
        }
        __syncthreads();
        #pragma unroll
        for (int kk = 0; kk < 32; kk++) {
            float a0 = As[kk][ty];
            float a1 = As[kk][ty + 16];
            float4 b = *reinterpret_cast<float4*>(&Bs[kk][tx << 2]);
            acc[0][0] += a0*b.x; acc[0][1] += a0*b.y;
            acc[0][2] += a0*b.z; acc[0][3] += a0*b.w;
            acc[1][0] += a1*b.x; acc[1][1] += a1*b.y;
            acc[1][2] += a1*b.z; acc[1][3] += a1*b.w;
        }
        __syncthreads();
    }

    int col = n0 + (tx << 2);
    #pragma unroll
    for (int i = 0; i < 2; i++) {
        int row = m0 + ty + i*16;
        #pragma unroll
        for (int j = 0; j < 4; j++) {
            if (col + j < N) {
                float vv = acc[i][j] + bias[col + j];
                if (act == 1)      vv = fmaxf(vv, 0.0f);
                else if (act == 2) vv = 1.0f / (1.0f + expf(-vv));
                C[(size_t)row*N + col + j] = vv;
            }
        }
    }
}

__global__ void gemm_kernel(const float* __restrict__ A, const float* __restrict__ B,
                            const float* __restrict__ bias, float* __restrict__ C,
                            int M, int N, int K, int act)
{
    gemm_body(A, B, bias, C, M, N, K, act, blockIdx.x, blockIdx.y);
}

// Two big GEMMs (w1 and wm1 heads) fused into one launch via gridDim.z to fill SMs.
__global__ void gemm_dual_kernel(const float* __restrict__ A,
    const float* __restrict__ B0, const float* __restrict__ bias0, float* __restrict__ C0,
    const float* __restrict__ B1, const float* __restrict__ bias1, float* __restrict__ C1,
    int M, int N, int K)
{
    if (blockIdx.z == 0)
        gemm_body(A, B0, bias0, C0, M, N, K, 1, blockIdx.x, blockIdx.y);
    else
        gemm_body(A, B1, bias1, C1, M, N, K, 1, blockIdx.x, blockIdx.y);
}

// ---------------------------------------------------------------------------
extern "C" void kernel_launch(void* const* d_in, const int* in_sizes, int n_in,
                              void* d_out, int out_size)
{
    const float* data = (const float*)d_in[0];
    const float* rois = (const float*)d_in[1];
    const float* w1   = (const float*)d_in[2];
    const float* b1   = (const float*)d_in[3];
    const float* w2   = (const float*)d_in[4];
    const float* b2   = (const float*)d_in[5];
    const float* w3   = (const float*)d_in[6];
    const float* b3   = (const float*)d_in[7];
    const float* wm1  = (const float*)d_in[8];
    const float* bm1  = (const float*)d_in[9];
    const float* wm2  = (const float*)d_in[10];
    const float* bm2  = (const float*)d_in[11];
    float* out = (float*)d_out;

    float *xpool, *h1, *m1, *h2, *offs, *maskp;
    cudaGetSymbolAddress((void**)&xpool, g_xpool);
    cudaGetSymbolAddress((void**)&h1,    g_h1);
    cudaGetSymbolAddress((void**)&m1,    g_m1);
    cudaGetSymbolAddress((void**)&h2,    g_h2);
    cudaGetSymbolAddress((void**)&offs,  g_offs);
    cudaGetSymbolAddress((void**)&maskp, g_mask);

    // 1) channel-last transpose of the feature map
    transpose_kernel<<<dim3(NB_HW/32, NB_C/32, NB_B), dim3(32,8)>>>(data);
    // 2) pool pass 1 (no trans) -> g_xpool
    pool_kernel<<<dim3(NB_BIN, NB_N), NB_C>>>(rois, out, 0);
    // 3) fused big GEMMs: x@w1+b1 relu -> h1 ; x@wm1+bm1 relu -> m1
    gemm_dual_kernel<<<dim3(NB_DF/64, NB_N/32, 2), 256>>>(
        xpool, w1, b1, h1, wm1, bm1, m1, NB_N, NB_DF, NB_KIN);
    // 4) h1@w2+b2 relu -> h2
    gemm_kernel<<<dim3(NB_DF/64, NB_N/32), 256>>>(h1, w2, b2, h2, NB_N, NB_DF, NB_DF, 1);
    // 5) h2@w3+b3 -> offsets (N,2,7,7)
    gemm_kernel<<<dim3(2, NB_N/32), 256>>>(h2, w3, b3, offs, NB_N, 98, NB_DF, 0);
    // 6) m1@wm2+bm2 sigmoid -> mask (N,7,7)
    gemm_kernel<<<dim3(1, NB_N/32), 256>>>(m1, wm2, bm2, maskp, NB_N, NB_BIN, NB_DF, 2);
    // 7) pool pass 2 (with offsets) * mask -> out (N,C,P,P)
    pool_kernel<<<dim3(NB_BIN, NB_N), NB_C>>>(rois, out, 1);
}

// round 2
// speedup vs baseline: 1.4524x; 1.4524x over previous
#include <cuda_runtime.h>
#include <math.h>
#include <stdint.h>

// Problem constants
#define NB_B   2
#define NB_C   128
#define NB_H   160
#define NB_W   160
#define NB_HW  (NB_H*NB_W)
#define NB_N   256
#define NB_P   7
#define NB_BIN 49
#define NB_KIN 6272     // C*P*P
#define NB_DF  1024
#define POOL_SCALE 0.0625f
#define TRANS_STD  0.1f

// Scratch (static device globals; no runtime allocation)
__device__ float g_dataT[NB_B*NB_HW*NB_C];   // (B,H,W,C) channel-last
__device__ float g_xpool[NB_N*NB_KIN];       // pooled features, layout [n][c*49+bin]
__device__ float g_h1[NB_N*NB_DF];
__device__ float g_m1[NB_N*NB_DF];
__device__ float g_h2[NB_N*NB_DF];
__device__ float g_offs[NB_N*98];            // (N,2,7,7) flattened
__device__ float g_mask[NB_N*NB_BIN];        // (N,7,7)

// ---------------------------------------------------------------------------
// (B,C,H,W) -> (B,H,W,C) tiled transpose
// ---------------------------------------------------------------------------
__global__ void transpose_kernel(const float* __restrict__ src)
{
    __shared__ float t[32][33];
    int b   = blockIdx.z;
    int hw0 = blockIdx.x * 32;
    int c0  = blockIdx.y * 32;
    #pragma unroll
    for (int i = 0; i < 4; i++) {
        int c = c0 + threadIdx.y + i*8;
        t[threadIdx.y + i*8][threadIdx.x] =
            src[(size_t)(b*NB_C + c)*NB_HW + hw0 + threadIdx.x];
    }
    __syncthreads();
    #pragma unroll
    for (int i = 0; i < 4; i++) {
        int hw = hw0 + threadIdx.y + i*8;
        g_dataT[(size_t)(b*NB_HW + hw)*NB_C + c0 + threadIdx.x] =
            t[threadIdx.x][threadIdx.y + i*8];
    }
}

// ---------------------------------------------------------------------------
// Deformable PSRoI pooling. One block per (bin, roi). 128 threads = channels.
// ---------------------------------------------------------------------------
__global__ void pool_kernel(const float* __restrict__ rois,
                            float* __restrict__ out, int second)
{
    __shared__ int   s_o[16], s_dx[16], s_dy[16];
    __shared__ float s_w0[16], s_w1[16], s_w2[16], s_w3[16], s_v[16];

    int bin = blockIdx.x;
    int n   = blockIdx.y;
    int tid = threadIdx.x;
    const float* r = rois + n*5;

    if (tid < 16) {
        int ph = bin / NB_P, pw = bin % NB_P;
        float x1 = rintf(r[1]) * POOL_SCALE - 0.5f;
        float y1 = rintf(r[2]) * POOL_SCALE - 0.5f;
        float x2 = (rintf(r[3]) + 1.0f) * POOL_SCALE - 0.5f;
        float y2 = (rintf(r[4]) + 1.0f) * POOL_SCALE - 0.5f;
        float roi_w = fmaxf(x2 - x1, 0.1f);
        float roi_h = fmaxf(y2 - y1, 0.1f);
        float bin_w = roi_w / (float)NB_P;
        float bin_h = roi_h / (float)NB_P;
        float sub_w = bin_w * 0.25f;
        float sub_h = bin_h * 0.25f;
        float tx = 0.0f, ty = 0.0f;
        if (second) {
            tx = g_offs[n*98 +      bin] * TRANS_STD;
            ty = g_offs[n*98 + 49 + bin] * TRANS_STD;
        }
        float wstart = (float)pw * bin_w + x1 + tx * roi_w;
        float hstart = (float)ph * bin_h + y1 + ty * roi_h;
        int iw = tid & 3, ih = tid >> 2;
        float w = wstart + (float)iw * sub_w;
        float h = hstart + (float)ih * sub_h;
        float v = (w >= -0.5f && w <= (float)NB_W - 0.5f &&
                   h >= -0.5f && h <= (float)NB_H - 0.5f) ? 1.0f : 0.0f;
        w = fminf(fmaxf(w, 0.0f), (float)(NB_W - 1));
        h = fminf(fmaxf(h, 0.0f), (float)(NB_H - 1));
        int x0  = (int)floorf(w);
        int y0  = (int)floorf(h);
        int x1i = min(x0 + 1, NB_W - 1);
        int y1i = min(y0 + 1, NB_H - 1);
        float lx = w - (float)x0;
        float ly = h - (float)y0;
        s_o [tid] = (y0*NB_W + x0) * NB_C;
        s_dx[tid] = (x1i - x0) * NB_C;
        s_dy[tid] = (y1i - y0) * NB_W * NB_C;
        s_w0[tid] = (1.0f-ly)*(1.0f-lx)*v;
        s_w1[tid] = (1.0f-ly)*lx*v;
        s_w2[tid] = ly*(1.0f-lx)*v;
        s_w3[tid] = ly*lx*v;
        s_v [tid] = v;
    }
    __syncthreads();

    float cnt = 0.0f;
    #pragma unroll
    for (int s = 0; s < 16; s++) cnt += s_v[s];

    int bi = (int)r[0];
    const float* base = g_dataT + (size_t)bi*NB_HW*NB_C + tid;  // channel = tid
    float acc = 0.0f;
    #pragma unroll
    for (int s = 0; s < 16; s++) {
        int o = s_o[s], dx = s_dx[s], dy = s_dy[s];
        acc += s_w0[s]*base[o]
             + s_w1[s]*base[o+dx]
             + s_w2[s]*base[o+dy]
             + s_w3[s]*base[o+dy+dx];
    }
    float res = (cnt > 0.0f) ? acc / cnt : 0.0f;
    if (second) {
        res *= g_mask[n*NB_BIN + bin];
        out[(size_t)(n*NB_C + tid)*NB_BIN + bin] = res;
    } else {
        g_xpool[(size_t)n*NB_KIN + tid*NB_BIN + bin] = res;
    }
}

// ---------------------------------------------------------------------------
// TF32 tensor-core GEMM: C(M,N) = act(A @ B + bias)
// Block: 128 threads = 4 warps (2x2). Tile BM=64, BN=64, BK=32.
// Warp tile 32x32 = 2(M) x 4(N) mma.m16n8k8. fp32 accumulate.
// Requires M%64==0, N%64==0, K%32==0.
// ---------------------------------------------------------------------------
__device__ __forceinline__ uint32_t f2tf(float x)
{
    uint32_t u;
    asm("cvt.rna.tf32.f32 %0, %1;" : "=r"(u) : "f"(x));
    return u;
}

__device__ __forceinline__ void mma_tf32(float (&d)[4], const uint32_t (&a)[4],
                                         const uint32_t (&b)[2])
{
    asm volatile(
        "mma.sync.aligned.m16n8k8.row.col.f32.tf32.tf32.f32 "
        "{%0,%1,%2,%3}, {%4,%5,%6,%7}, {%8,%9}, {%0,%1,%2,%3};\n"
        : "+f"(d[0]), "+f"(d[1]), "+f"(d[2]), "+f"(d[3])
        : "r"(a[0]), "r"(a[1]), "r"(a[2]), "r"(a[3]), "r"(b[0]), "r"(b[1]));
}

__device__ __forceinline__ void gemm_tf32_body(
    const float* __restrict__ A, const float* __restrict__ B,
    const float* __restrict__ bias, float* __restrict__ C,
    int M, int N, int K, int act, int bx, int by)
{
    __shared__ uint32_t As[64][36];   // [row][k]  bank = (4r+k)%32 -> frag LDS conflict-free
    __shared__ uint32_t Bs[32][72];   // [k][col]  bank = (8k+n)%32 -> frag LDS conflict-free

    int tid  = threadIdx.x;
    int lane = tid & 31;
    int warp = tid >> 5;
    int wm = warp & 1, wn = warp >> 1;
    int g = lane >> 2, tig = lane & 3;
    int m0 = by * 64, n0 = bx * 64;

    // A gmem mapping: row = tid>>1 (0..63), k-cols (tid&1)*4 + 8j
    int ar  = tid >> 1;
    int ac0 = (tid & 1) * 4;
    const float* Ag = A + (size_t)(m0 + ar) * K + ac0;
    // B gmem mapping: k = tid>>2 (0..31), cols (tid&3)*4 + 16j
    int bk  = tid >> 2;
    int bc0 = (tid & 3) * 4;
    const float* Bg = B + (size_t)bk * N + n0 + bc0;

    float4 av[4], bv[4];
    #pragma unroll
    for (int j = 0; j < 4; j++) av[j] = *(const float4*)(Ag + 8*j);
    #pragma unroll
    for (int j = 0; j < 4; j++) bv[j] = *(const float4*)(Bg + 16*j);

    float acc[2][4][4];
    #pragma unroll
    for (int mi = 0; mi < 2; mi++)
        #pragma unroll
        for (int ni = 0; ni < 4; ni++)
            #pragma unroll
            for (int q = 0; q < 4; q++) acc[mi][ni][q] = 0.0f;

    int nk = K / 32;
    for (int t = 0; t < nk; t++) {
        // store prefetched tile (with tf32 conversion)
        #pragma unroll
        for (int j = 0; j < 4; j++) {
            uint4 u = make_uint4(f2tf(av[j].x), f2tf(av[j].y),
                                 f2tf(av[j].z), f2tf(av[j].w));
            *(uint4*)&As[ar][ac0 + 8*j] = u;
        }
        #pragma unroll
        for (int j = 0; j < 4; j++) {
            uint4 u = make_uint4(f2tf(bv[j].x), f2tf(bv[j].y),
                                 f2tf(bv[j].z), f2tf(bv[j].w));
            *(uint4*)&Bs[bk][bc0 + 16*j] = u;
        }
        __syncthreads();

        // prefetch next tile (LDG overlaps with compute below)
        if (t + 1 < nk) {
            const float* Ag2 = Ag + (t + 1) * 32;
            const float* Bg2 = Bg + (size_t)(t + 1) * 32 * N;
            #pragma unroll
            for (int j = 0; j < 4; j++) av[j] = *(const float4*)(Ag2 + 8*j);
            #pragma unroll
            for (int j = 0; j < 4; j++) bv[j] = *(const float4*)(Bg2 + 16*j);
        }

        #pragma unroll
        for (int kk = 0; kk < 32; kk += 8) {
            uint32_t a[2][4], b[4][2];
            #pragma unroll
            for (int mi = 0; mi < 2; mi++) {
                int rb = wm*32 + mi*16;
                a[mi][0] = As[rb + g    ][kk + tig];
                a[mi][1] = As[rb + g + 8][kk + tig];
                a[mi][2] = As[rb + g    ][kk + tig + 4];
                a[mi][3] = As[rb + g + 8][kk + tig + 4];
            }
            #pragma unroll
            for (int ni = 0; ni < 4; ni++) {
                int cn = wn*32 + ni*8 + g;
                b[ni][0] = Bs[kk + tig    ][cn];
                b[ni][1] = Bs[kk + tig + 4][cn];
            }
            #pragma unroll
            for (int mi = 0; mi < 2; mi++)
                #pragma unroll
                for (int ni = 0; ni < 4; ni++)
                    mma_tf32(acc[mi][ni], a[mi], b[ni]);
        }
        __syncthreads();
    }

    // epilogue: bias + activation, direct to gmem
    #pragma unroll
    for (int mi = 0; mi < 2; mi++) {
        int row0 = m0 + wm*32 + mi*16 + g;
        #pragma unroll
        for (int ni = 0; ni < 4; ni++) {
            int col = n0 + wn*32 + ni*8 + tig*2;
            float bz0 = bias[col], bz1 = bias[col + 1];
            float v0 = acc[mi][ni][0] + bz0;
            float v1 = acc[mi][ni][1] + bz1;
            float v2 = acc[mi][ni][2] + bz0;
            float v3 = acc[mi][ni][3] + bz1;
            if (act == 1) {
                v0 = fmaxf(v0, 0.f); v1 = fmaxf(v1, 0.f);
                v2 = fmaxf(v2, 0.f); v3 = fmaxf(v3, 0.f);
            }
            C[(size_t)row0*N + col]           = v0;
            C[(size_t)row0*N + col + 1]       = v1;
            C[(size_t)(row0 + 8)*N + col]     = v2;
            C[(size_t)(row0 + 8)*N + col + 1] = v3;
        }
    }
}

__global__ void __launch_bounds__(128)
gemm_tf32_kernel(const float* __restrict__ A, const float* __restrict__ B,
                 const float* __restrict__ bias, float* __restrict__ C,
                 int M, int N, int K, int act)
{
    gemm_tf32_body(A, B, bias, C, M, N, K, act, blockIdx.x, blockIdx.y);
}

__global__ void __launch_bounds__(128)
gemm_tf32_dual_kernel(const float* __restrict__ A,
    const float* __restrict__ B0, const float* __restrict__ bias0, float* __restrict__ C0,
    const float* __restrict__ B1, const float* __restrict__ bias1, float* __restrict__ C1,
    int M, int N, int K)
{
    if (blockIdx.z == 0)
        gemm_tf32_body(A, B0, bias0, C0, M, N, K, 1, blockIdx.x, blockIdx.y);
    else
        gemm_tf32_body(A, B1, bias1, C1, M, N, K, 1, blockIdx.x, blockIdx.y);
}

// ---------------------------------------------------------------------------
// fp32 tiled GEMM (kept for the small N=98 / N=49 heads)
// ---------------------------------------------------------------------------
__device__ __forceinline__ void gemm_body(
    const float* __restrict__ A, const float* __restrict__ B,
    const float* __restrict__ bias, float* __restrict__ C,
    int M, int N, int K, int act, int bx, int by)
{
    __shared__ float As[32][33];
    __shared__ float Bs[32][64];
    int tid = threadIdx.x;
    int tx = tid & 15, ty = tid >> 4;
    int m0 = by * 32, n0 = bx * 64;
    int arow = tid >> 3;
    int acol = (tid & 7) << 2;
    int brow = tid >> 4;
    int bcol = (tid & 15) << 2;
    bool nvec = ((N & 3) == 0);

    float acc[2][4] = {{0.f,0.f,0.f,0.f},{0.f,0.f,0.f,0.f}};

    for (int k0 = 0; k0 < K; k0 += 32) {
        float4 av = *reinterpret_cast<const float4*>(
            A + (size_t)(m0 + arow)*K + k0 + acol);
        As[acol+0][arow] = av.x; As[acol+1][arow] = av.y;
        As[acol+2][arow] = av.z; As[acol+3][arow] = av.w;
        #pragma unroll
        for (int rr = 0; rr < 2; rr++) {
            int kk = brow + rr*16;
            const float* bp = B + (size_t)(k0 + kk)*N + n0 + bcol;
            float4 bv;
            if (nvec && (n0 + bcol + 3 < N)) {
                bv = *reinterpret_cast<const float4*>(bp);
            } else {
                bv.x = (n0+bcol+0 < N) ? bp[0] : 0.0f;
                bv.y = (n0+bcol+1 < N) ? bp[1] : 0.0f;
                bv.z = (n0+bcol+2 < N) ? bp[2] : 0.0f;
                bv.w = (n0+bcol+3 < N) ? bp[3] : 0.0f;
            }
            *reinterpret_cast<float4*>(&Bs[kk][bcol]) = bv;
        }
        __syncthreads();
        #pragma unroll
        for (int kk = 0; kk < 32; kk++) {
            float a0 = As[kk][ty];
            float a1 = As[kk][ty + 16];
            float4 b = *reinterpret_cast<float4*>(&Bs[kk][tx << 2]);
            acc[0][0] += a0*b.x; acc[0][1] += a0*b.y;
            acc[0][2] += a0*b.z; acc[0][3] += a0*b.w;
            acc[1][0] += a1*b.x; acc[1][1] += a1*b.y;
            acc[1][2] += a1*b.z; acc[1][3] += a1*b.w;
        }
        __syncthreads();
    }

    int col = n0 + (tx << 2);
    #pragma unroll
    for (int i = 0; i < 2; i++) {
        int row = m0 + ty + i*16;
        #pragma unroll
        for (int j = 0; j < 4; j++) {
            if (col + j < N) {
                float vv = acc[i][j] + bias[col + j];
                if (act == 1)      vv = fmaxf(vv, 0.0f);
                else if (act == 2) vv = 1.0f / (1.0f + expf(-vv));
                C[(size_t)row*N + col + j] = vv;
            }
        }
    }
}

__global__ void gemm_kernel(const float* __restrict__ A, const float* __restrict__ B,
                            const float* __restrict__ bias, float* __restrict__ C,
                            int M, int N, int K, int act)
{
    gemm_body(A, B, bias, C, M, N, K, act, blockIdx.x, blockIdx.y);
}

// ---------------------------------------------------------------------------
extern "C" void kernel_launch(void* const* d_in, const int* in_sizes, int n_in,
                              void* d_out, int out_size)
{
    const float* data = (const float*)d_in[0];
    const float* rois = (const float*)d_in[1];
    const float* w1   = (const float*)d_in[2];
    const float* b1   = (const float*)d_in[3];
    const float* w2   = (const float*)d_in[4];
    const float* b2   = (const float*)d_in[5];
    const float* w3   = (const float*)d_in[6];
    const float* b3   = (const float*)d_in[7];
    const float* wm1  = (const float*)d_in[8];
    const float* bm1  = (const float*)d_in[9];
    const float* wm2  = (const float*)d_in[10];
    const float* bm2  = (const float*)d_in[11];
    float* out = (float*)d_out;

    float *xpool, *h1, *m1, *h2, *offs, *maskp;
    cudaGetSymbolAddress((void**)&xpool, g_xpool);
    cudaGetSymbolAddress((void**)&h1,    g_h1);
    cudaGetSymbolAddress((void**)&m1,    g_m1);
    cudaGetSymbolAddress((void**)&h2,    g_h2);
    cudaGetSymbolAddress((void**)&offs,  g_offs);
    cudaGetSymbolAddress((void**)&maskp, g_mask);

    // 1) channel-last transpose of the feature map
    transpose_kernel<<<dim3(NB_HW/32, NB_C/32, NB_B), dim3(32,8)>>>(data);
    // 2) pool pass 1 (no trans) -> g_xpool
    pool_kernel<<<dim3(NB_BIN, NB_N), NB_C>>>(rois, out, 0);
    // 3) fused big GEMMs (TF32 tensor cores): x@w1 relu -> h1 ; x@wm1 relu -> m1
    gemm_tf32_dual_kernel<<<dim3(NB_DF/64, NB_N/64, 2), 128>>>(
        xpool, w1, b1, h1, wm1, bm1, m1, NB_N, NB_DF, NB_KIN);
    // 4) h1@w2+b2 relu -> h2 (TF32)
    gemm_tf32_kernel<<<dim3(NB_DF/64, NB_N/64), 128>>>(h1, w2, b2, h2, NB_N, NB_DF, NB_DF, 1);
    // 5) h2@w3+b3 -> offsets (N,2,7,7)  [fp32, tiny]
    gemm_kernel<<<dim3(2, NB_N/32), 256>>>(h2, w3, b3, offs, NB_N, 98, NB_DF, 0);
    // 6) m1@wm2+bm2 sigmoid -> mask (N,7,7)  [fp32, tiny]
    gemm_kernel<<<dim3(1, NB_N/32), 256>>>(m1, wm2, bm2, maskp, NB_N, NB_BIN, NB_DF, 2);
    // 7) pool pass 2 (with offsets) * mask -> out (N,C,P,P)
    pool_kernel<<<dim3(NB_BIN, NB_N), NB_C>>>(rois, out, 1);
}

// round 4
// speedup vs baseline: 3.2071x; 2.2081x over previous
#include <cuda_runtime.h>
#include <math.h>
#include <stdint.h>

// Problem constants
#define NB_B   2
#define NB_C   128
#define NB_H   160
#define NB_W   160
#define NB_HW  (NB_H*NB_W)
#define NB_N   256
#define NB_P   7
#define NB_BIN 49
#define NB_KIN 6272     // C*P*P
#define NB_DF  1024
#define POOL_SCALE 0.0625f
#define TRANS_STD  0.1f

#define NSTG 4          // cp.async pipeline stages

// Scratch (static device globals; no runtime allocation)
__device__ __align__(16) float g_dataT[NB_B*NB_HW*NB_C];   // (B,H,W,C)
__device__ __align__(16) float g_xpool[NB_N*NB_KIN];       // [n][c*49+bin]
__device__ __align__(16) float g_h1[NB_N*NB_DF];
__device__ __align__(16) float g_m1[NB_N*NB_DF];
__device__ __align__(16) float g_h2[NB_N*NB_DF];
__device__ __align__(16) float g_w3p[NB_DF*128];           // w3 padded N 98->128
__device__ __align__(16) float g_wm2p[NB_DF*64];           // wm2 padded N 49->64
__device__ float g_offs[NB_N*98];
__device__ float g_mask[NB_N*NB_BIN];

// ---------------------------------------------------------------------------
// (B,C,H,W) -> (B,H,W,C) tiled transpose
// ---------------------------------------------------------------------------
__global__ void transpose_kernel(const float* __restrict__ src)
{
    __shared__ float t[32][33];
    int b   = blockIdx.z;
    int hw0 = blockIdx.x * 32;
    int c0  = blockIdx.y * 32;
    #pragma unroll
    for (int i = 0; i < 4; i++) {
        int c = c0 + threadIdx.y + i*8;
        t[threadIdx.y + i*8][threadIdx.x] =
            src[(size_t)(b*NB_C + c)*NB_HW + hw0 + threadIdx.x];
    }
    __syncthreads();
    #pragma unroll
    for (int i = 0; i < 4; i++) {
        int hw = hw0 + threadIdx.y + i*8;
        g_dataT[(size_t)(b*NB_HW + hw)*NB_C + c0 + threadIdx.x] =
            t[threadIdx.x][threadIdx.y + i*8];
    }
}

// ---------------------------------------------------------------------------
// Deformable PSRoI pooling. ONE WARP per (bin, roi). Lane owns 4 channels
// (float4). Sample params computed per-lane (lanes 0-15 meaningful) and
// broadcast with shfl — no smem, no block barriers.
// ---------------------------------------------------------------------------
__global__ void __launch_bounds__(32)
pool_kernel(const float* __restrict__ rois, float* __restrict__ out, int second)
{
    int bin  = blockIdx.x;
    int n    = blockIdx.y;
    int lane = threadIdx.x;
    const float* r = rois + n*5;

    int ph = bin / NB_P, pw = bin % NB_P;
    float x1 = rintf(r[1]) * POOL_SCALE - 0.5f;
    float y1 = rintf(r[2]) * POOL_SCALE - 0.5f;
    float x2 = (rintf(r[3]) + 1.0f) * POOL_SCALE - 0.5f;
    float y2 = (rintf(r[4]) + 1.0f) * POOL_SCALE - 0.5f;
    float roi_w = fmaxf(x2 - x1, 0.1f);
    float roi_h = fmaxf(y2 - y1, 0.1f);
    float bin_w = roi_w / (float)NB_P;
    float bin_h = roi_h / (float)NB_P;
    float sub_w = bin_w * 0.25f;
    float sub_h = bin_h * 0.25f;
    float tx = 0.0f, ty = 0.0f;
    if (second) {
        tx = g_offs[n*98 +      bin] * TRANS_STD;
        ty = g_offs[n*98 + 49 + bin] * TRANS_STD;
    }
    float wstart = (float)pw * bin_w + x1 + tx * roi_w;
    float hstart = (float)ph * bin_h + y1 + ty * roi_h;

    // per-lane sample (lanes 16-31 duplicate 0-15; harmless)
    int iw = lane & 3, ih = (lane >> 2) & 3;
    float w = wstart + (float)iw * sub_w;
    float h = hstart + (float)ih * sub_h;
    float v = (w >= -0.5f && w <= (float)NB_W - 0.5f &&
               h >= -0.5f && h <= (float)NB_H - 0.5f) ? 1.0f : 0.0f;
    w = fminf(fmaxf(w, 0.0f), (float)(NB_W - 1));
    h = fminf(fmaxf(h, 0.0f), (float)(NB_H - 1));
    int x0  = (int)floorf(w);
    int y0  = (int)floorf(h);
    int x1i = min(x0 + 1, NB_W - 1);
    int y1i = min(y0 + 1, NB_H - 1);
    float lx = w - (float)x0;
    float ly = h - (float)y0;
    float w0 = (1.0f-ly)*(1.0f-lx)*v;
    float w1 = (1.0f-ly)*lx*v;
    float w2 = ly*(1.0f-lx)*v;
    float w3 = ly*lx*v;
    // offsets in float4 units (channel stride NB_C floats = 32 float4)
    int o4  = ((y0*NB_W + x0) * NB_C) >> 2;
    int dx4 = ((x1i - x0) * NB_C) >> 2;
    int dy4 = ((y1i - y0) * NB_W * NB_C) >> 2;

    int bi = (int)r[0];
    const float4* base = reinterpret_cast<const float4*>(
        g_dataT + (size_t)bi*NB_HW*NB_C) + lane;

    float4 acc = make_float4(0.f, 0.f, 0.f, 0.f);
    float cnt = 0.0f;
    #pragma unroll
    for (int s = 0; s < 16; s++) {
        float W0 = __shfl_sync(0xffffffffu, w0, s);
        float W1 = __shfl_sync(0xffffffffu, w1, s);
        float W2 = __shfl_sync(0xffffffffu, w2, s);
        float W3 = __shfl_sync(0xffffffffu, w3, s);
        float V  = __shfl_sync(0xffffffffu, v,  s);
        int O    = __shfl_sync(0xffffffffu, o4, s);
        int DX   = __shfl_sync(0xffffffffu, dx4, s);
        int DY   = __shfl_sync(0xffffffffu, dy4, s);
        cnt += V;
        float4 p00 = base[O];
        float4 p01 = base[O + DX];
        float4 p10 = base[O + DY];
        float4 p11 = base[O + DY + DX];
        acc.x += W0*p00.x + W1*p01.x + W2*p10.x + W3*p11.x;
        acc.y += W0*p00.y + W1*p01.y + W2*p10.y + W3*p11.y;
        acc.z += W0*p00.z + W1*p01.z + W2*p10.z + W3*p11.z;
        acc.w += W0*p00.w + W1*p01.w + W2*p10.w + W3*p11.w;
    }
    float inv = (cnt > 0.0f) ? 1.0f/cnt : 0.0f;
    acc.x *= inv; acc.y *= inv; acc.z *= inv; acc.w *= inv;

    int ch = lane * 4;
    if (second) {
        float mv = g_mask[n*NB_BIN + bin];
        acc.x *= mv; acc.y *= mv; acc.z *= mv; acc.w *= mv;
        float* op = out + (size_t)(n*NB_C + ch)*NB_BIN + bin;
        op[0*NB_BIN] = acc.x; op[1*NB_BIN] = acc.y;
        op[2*NB_BIN] = acc.z; op[3*NB_BIN] = acc.w;
    } else {
        float* xp = g_xpool + (size_t)n*NB_KIN + ch*NB_BIN + bin;
        xp[0*NB_BIN] = acc.x; xp[1*NB_BIN] = acc.y;
        xp[2*NB_BIN] = acc.z; xp[3*NB_BIN] = acc.w;
    }
}

// ---------------------------------------------------------------------------
// Weight padding for small heads (zero-fill extra columns)
// ---------------------------------------------------------------------------
__global__ void pad_kernel(const float* __restrict__ src, float* __restrict__ dst,
                           int srcN, int dstN)
{
    int i = blockIdx.x * 256 + threadIdx.x;      // over K*dstN
    int k = i / dstN, j = i % dstN;
    dst[i] = (j < srcN) ? src[k*srcN + j] : 0.0f;
}

// ---------------------------------------------------------------------------
// Pipelined TF32 tensor-core GEMM.
// Block: 128 threads = 4 warps. BN=64, BK=32, BM template (64 or 32).
// cp.async 4-stage pipeline, fragment double-buffering, no cvt (HW truncation).
// ---------------------------------------------------------------------------
__device__ __forceinline__ void mma_tf32(float (&d)[4], const uint32_t (&a)[4],
                                         const uint32_t (&b)[2])
{
    asm volatile(
        "mma.sync.aligned.m16n8k8.row.col.f32.tf32.tf32.f32 "
        "{%0,%1,%2,%3}, {%4,%5,%6,%7}, {%8,%9}, {%0,%1,%2,%3};\n"
        : "+f"(d[0]), "+f"(d[1]), "+f"(d[2]), "+f"(d[3])
        : "r"(a[0]), "r"(a[1]), "r"(a[2]), "r"(a[3]), "r"(b[0]), "r"(b[1]));
}

__device__ __forceinline__ void cp16(uint32_t dst, const float* src)
{
    asm volatile("cp.async.cg.shared.global [%0], [%1], 16;" :: "r"(dst), "l"(src));
}
__device__ __forceinline__ void cp_commit()
{
    asm volatile("cp.async.commit_group;");
}
template<int n> __device__ __forceinline__ void cp_wait()
{
    asm volatile("cp.async.wait_group %0;" :: "n"(n));
}

template<int BM>
__device__ __forceinline__ void gemm_pipe_body(
    const float* __restrict__ A, const float* __restrict__ B,
    const float* __restrict__ bias, float* __restrict__ C,
    int N, int K, int ldc, int realN, int act,
    int bx, int by, uint32_t* sm)
{
    constexpr int ASZ = BM*36;          // As: [BM][36]  bank-conflict-free frag LDS
    constexpr int BSZ = 32*72;          // Bs: [32][72]
    constexpr int STG = ASZ + BSZ;
    constexpr int WNT = (BM == 64) ? 4 : 2;   // n-tiles (8 wide) per warp
    constexpr int TPR = 128/BM;         // threads per A row
    constexpr int ACH = 32/(TPR*4);     // float4 chunks per thread (A)

    int tid  = threadIdx.x;
    int lane = tid & 31;
    int warp = tid >> 5;
    int g = lane >> 2, tig = lane & 3;
    int m0 = by * BM, n0 = bx * 64;
    int warp_row = (BM == 64) ? (warp & 1) * 32 : 0;
    int warp_col = (BM == 64) ? (warp >> 1) * 32 : warp * 16;

    int ar  = tid / TPR;
    int ac0 = (tid % TPR) * 4;
    int bk  = tid >> 2;
    int bc0 = (tid & 3) * 4;

    const float* Ab = A + (size_t)(m0 + ar) * K + ac0;
    const float* Bb = B + (size_t)bk * N + n0 + bc0;
    uint32_t sbase = (uint32_t)__cvta_generic_to_shared(sm);

    int nk = K / 32;

    auto issue = [&](int t) {
        uint32_t as = sbase + (uint32_t)((t % NSTG) * STG) * 4u;
        uint32_t bs = as + ASZ * 4u;
        const float* Ap = Ab + t * 32;
        const float* Bp = Bb + (size_t)t * 32 * N;
        #pragma unroll
        for (int j = 0; j < ACH; j++)
            cp16(as + (uint32_t)(ar*36 + ac0 + TPR*4*j) * 4u, Ap + TPR*4*j);
        #pragma unroll
        for (int j = 0; j < 4; j++)
            cp16(bs + (uint32_t)(bk*72 + bc0 + 16*j) * 4u, Bp + 16*j);
    };

    #pragma unroll
    for (int s = 0; s < NSTG-1; s++) { if (s < nk) issue(s); cp_commit(); }

    float acc[2][WNT][4] = {};
    uint32_t af[2][2][4], bf[2][WNT][2];

    for (int t = 0; t < nk; t++) {
        cp_wait<NSTG-2>();
        __syncthreads();
        if (t + NSTG-1 < nk) issue(t + NSTG-1);
        cp_commit();

        const uint32_t* As = sm + (t % NSTG) * STG;
        const uint32_t* Bs = As + ASZ;

        auto loadf = [&](int kk, int bi2) {
            #pragma unroll
            for (int mi = 0; mi < 2; mi++) {
                int rb = warp_row + mi*16;
                af[bi2][mi][0] = As[(rb + g    )*36 + kk + tig];
                af[bi2][mi][1] = As[(rb + g + 8)*36 + kk + tig];
                af[bi2][mi][2] = As[(rb + g    )*36 + kk + tig + 4];
                af[bi2][mi][3] = As[(rb + g + 8)*36 + kk + tig + 4];
            }
            #pragma unroll
            for (int ni = 0; ni < WNT; ni++) {
                int cn = warp_col + ni*8 + g;
                bf[bi2][ni][0] = Bs[(kk + tig    )*72 + cn];
                bf[bi2][ni][1] = Bs[(kk + tig + 4)*72 + cn];
            }
        };

        loadf(0, 0);
        #pragma unroll
        for (int ks = 0; ks < 4; ks++) {
            if (ks < 3) loadf((ks+1)*8, (ks+1) & 1);
            #pragma unroll
            for (int mi = 0; mi < 2; mi++)
                #pragma unroll
                for (int ni = 0; ni < WNT; ni++)
                    mma_tf32(acc[mi][ni], af[ks & 1][mi], bf[ks & 1][ni]);
        }
        // no trailing sync: this stage's smem is only overwritten after the
        // next iteration's barrier (4-stage ring).
    }

    #pragma unroll
    for (int mi = 0; mi < 2; mi++) {
        int row0 = m0 + warp_row + mi*16 + g;
        #pragma unroll
        for (int ni = 0; ni < WNT; ni++) {
            int col = n0 + warp_col + ni*8 + tig*2;
            #pragma unroll
            for (int half = 0; half < 2; half++) {
                int cc = col + half;
                if (cc < realN) {
                    float v0 = acc[mi][ni][half]     + bias[cc];
                    float v1 = acc[mi][ni][half + 2] + bias[cc];
                    if (act == 1) { v0 = fmaxf(v0, 0.f); v1 = fmaxf(v1, 0.f); }
                    else if (act == 2) {
                        v0 = 1.0f/(1.0f + __expf(-v0));
                        v1 = 1.0f/(1.0f + __expf(-v1));
                    }
                    C[(size_t)row0*ldc + cc]       = v0;
                    C[(size_t)(row0+8)*ldc + cc]   = v1;
                }
            }
        }
    }
}

template<int BM>
__global__ void __launch_bounds__(128)
gemm_pipe_kernel(const float* __restrict__ A, const float* __restrict__ B,
                 const float* __restrict__ bias, float* __restrict__ C,
                 int N, int K, int ldc, int realN, int act)
{
    extern __shared__ uint32_t sm[];
    gemm_pipe_body<BM>(A, B, bias, C, N, K, ldc, realN, act,
                       blockIdx.x, blockIdx.y, sm);
}

__global__ void __launch_bounds__(128)
gemm_pipe_dual(const float* __restrict__ A,
               const float* __restrict__ B0, const float* __restrict__ bi0, float* __restrict__ C0,
               const float* __restrict__ B1, const float* __restrict__ bi1, float* __restrict__ C1,
               int N, int K)
{
    extern __shared__ uint32_t sm[];
    if (blockIdx.z == 0)
        gemm_pipe_body<64>(A, B0, bi0, C0, N, K, N, N, 1, blockIdx.x, blockIdx.y, sm);
    else
        gemm_pipe_body<64>(A, B1, bi1, C1, N, K, N, N, 1, blockIdx.x, blockIdx.y, sm);
}

// ---------------------------------------------------------------------------
extern "C" void kernel_launch(void* const* d_in, const int* in_sizes, int n_in,
                              void* d_out, int out_size)
{
    const float* data = (const float*)d_in[0];
    const float* rois = (const float*)d_in[1];
    const float* w1   = (const float*)d_in[2];
    const float* b1   = (const float*)d_in[3];
    const float* w2   = (const float*)d_in[4];
    const float* b2   = (const float*)d_in[5];
    const float* w3   = (const float*)d_in[6];
    const float* b3   = (const float*)d_in[7];
    const float* wm1  = (const float*)d_in[8];
    const float* bm1  = (const float*)d_in[9];
    const float* wm2  = (const float*)d_in[10];
    const float* bm2  = (const float*)d_in[11];
    float* out = (float*)d_out;

    float *xpool, *h1, *m1, *h2, *offs, *maskp, *w3p, *wm2p;
    cudaGetSymbolAddress((void**)&xpool, g_xpool);
    cudaGetSymbolAddress((void**)&h1,    g_h1);
    cudaGetSymbolAddress((void**)&m1,    g_m1);
    cudaGetSymbolAddress((void**)&h2,    g_h2);
    cudaGetSymbolAddress((void**)&offs,  g_offs);
    cudaGetSymbolAddress((void**)&maskp, g_mask);
    cudaGetSymbolAddress((void**)&w3p,   g_w3p);
    cudaGetSymbolAddress((void**)&wm2p,  g_wm2p);

    const int SMEM64 = NSTG * (64*36 + 32*72) * 4;   // 73728 B
    const int SMEM32 = NSTG * (32*36 + 32*72) * 4;   // 55296 B
    cudaFuncSetAttribute(gemm_pipe_dual,
        cudaFuncAttributeMaxDynamicSharedMemorySize, SMEM64);
    cudaFuncSetAttribute(gemm_pipe_kernel<32>,
        cudaFuncAttributeMaxDynamicSharedMemorySize, SMEM32);

    // 1) channel-last transpose
    transpose_kernel<<<dim3(NB_HW/32, NB_C/32, NB_B), dim3(32,8)>>>(data);
    // 1b) pad small-head weights (independent)
    pad_kernel<<<NB_DF*128/256, 256>>>(w3,  w3p,  98, 128);
    pad_kernel<<<NB_DF*64/256,  256>>>(wm2, wm2p, 49, 64);
    // 2) pool pass 1 -> g_xpool  (one warp per (bin, roi))
    pool_kernel<<<dim3(NB_BIN, NB_N), 32>>>(rois, out, 0);
    // 3) fused big GEMMs: x@w1 relu -> h1 ; x@wm1 relu -> m1
    gemm_pipe_dual<<<dim3(NB_DF/64, NB_N/64, 2), 128, SMEM64>>>(
        xpool, w1, b1, h1, wm1, bm1, m1, NB_DF, NB_KIN);
    // 4) h1@w2 relu -> h2  (BM=32 -> 128 blocks)
    gemm_pipe_kernel<32><<<dim3(NB_DF/64, NB_N/32), 128, SMEM32>>>(
        h1, w2, b2, h2, NB_DF, NB_DF, NB_DF, NB_DF, 1);
    // 5) h2@w3p -> offsets (N padded 128, real 98)
    gemm_pipe_kernel<32><<<dim3(2, NB_N/32), 128, SMEM32>>>(
        h2, w3p, b3, offs, 128, NB_DF, 98, 98, 0);
    // 6) m1@wm2p sigmoid -> mask (N padded 64, real 49)
    gemm_pipe_kernel<32><<<dim3(1, NB_N/32), 128, SMEM32>>>(
        m1, wm2p, bm2, maskp, 64, NB_DF, 49, 49, 2);
    // 7) pool pass 2 * mask -> out
    pool_kernel<<<dim3(NB_BIN, NB_N), 32>>>(rois, out, 1);
}